// round 8
// baseline (speedup 1.0000x reference)
#include <cuda_runtime.h>
#include <cuda_bf16.h>

#define NLVL   4
#define BATCH  4
#define NBOX   128
#define MAXBS  64
#define CROP   14
#define CCH    256
#define NSLOTS (NLVL * BATCH * MAXBS)          // 1024
#define PTS    (CROP * CROP)                   // 196
#define C4     (CCH / 4)                       // 64 float4 per point
#define NT     (PTS / 4)                       // 49 tiles of 4 points per slot

// slot -> source box index (n in 0..127), or -1 if the slot is empty.
__device__ int g_slot_map[NSLOTS];

// ---------------------------------------------------------------------------
// Setup: 16 warps, one per (batch, level). Warp-ballot prefix scan.
// ---------------------------------------------------------------------------
__global__ void __launch_bounds__(512)
setup_kernel(const float* __restrict__ db, float* __restrict__ out_boxes) {
    int w    = threadIdx.x >> 5;
    int lane = threadIdx.x & 31;
    int b    = w >> 2;
    int lvl  = w & 3;
    float flvl = (float)lvl;

    int rank_base = 0;
    #pragma unroll
    for (int k = 0; k < 4; ++k) {
        int n = k * 32 + lane;
        float id = db[(b * NBOX + n) * 7 + 0];
        bool m = (id == flvl);
        unsigned mask = __ballot_sync(0xffffffffu, m);
        int rank = rank_base + __popc(mask & ((1u << lane) - 1u));
        if (m && rank < MAXBS) {
            g_slot_map[(lvl * BATCH + b) * MAXBS + rank] = n;
            float* ob = out_boxes + ((size_t)(b * NLVL + lvl) * MAXBS + rank) * 6;
            const float* src = db + (b * NBOX + n) * 7 + 1;
            #pragma unroll
            for (int q = 0; q < 6; ++q) ob[q] = src[q];
        }
        rank_base += __popc(mask);
    }
    int filled = rank_base < MAXBS ? rank_base : MAXBS;
    for (int r = filled + lane; r < MAXBS; r += 32) {
        g_slot_map[(lvl * BATCH + b) * MAXBS + r] = -1;
        float* ob = out_boxes + ((size_t)(b * NLVL + lvl) * MAXBS + r) * 6;
        #pragma unroll
        for (int q = 0; q < 6; ++q) ob[q] = 0.0f;
    }
}

// ---------------------------------------------------------------------------
// Main: one block per slot. 256 threads = (pin 0..3) x (c4 0..63).
// Phase 1: threads 0..195 precompute all 196 points' corner offsets + weights.
// Phase 2: loop 49 tiles with a 2-stage register pipeline; last iter peeled.
// __launch_bounds__(256, 6) caps regs at 40 -> 6 blocks/SM.
// ---------------------------------------------------------------------------
__global__ void __launch_bounds__(256, 6)
roi_kernel(const float* __restrict__ f0, const float* __restrict__ f1,
           const float* __restrict__ f2, const float* __restrict__ f3,
           const float* __restrict__ db, float* __restrict__ out) {
    __shared__ int4   s_off[PTS];   // o00,o01,o10,o11 (float4 units)
    __shared__ float2 s_w[PTS];     // wx, wy
    __shared__ int    s_vld[PTS];

    int slotIdx = blockIdx.x;
    int pin     = threadIdx.x >> 6;           // point within tile (0..3)
    int c4      = threadIdx.x & 63;

    float4* base = reinterpret_cast<float4*>(out)
                 + (size_t)slotIdx * (PTS * C4) + pin * C4 + c4;
    const int TS = 4 * C4;                    // tile stride in float4

    int n = g_slot_map[slotIdx];              // uniform across block

    if (n < 0) {                              // empty slot: streaming zeros
        float4 z = make_float4(0.f, 0.f, 0.f, 0.f);
        #pragma unroll 7
        for (int t = 0; t < NT; ++t) __stcs(base + t * TS, z);
        return;
    }

    int lvl = slotIdx >> 8;
    int b   = (slotIdx >> 6) & 3;
    int H   = 256 >> lvl;

    if (threadIdx.x < PTS) {
        const float* bx = db + (b * NBOX + n) * 7;
        float cx = bx[1], cy = bx[2], w = bx[3], h = bx[4];

        float y1n = (cy - h * 0.5f) / 1023.0f;
        float y2n = (cy + h * 0.5f) / 1023.0f;
        float x1n = (cx - w * 0.5f) / 1023.0f;
        float x2n = (cx + w * 0.5f) / 1023.0f;

        float S = (float)(H - 1);
        int pt  = threadIdx.x;
        int py  = pt / CROP;
        int px  = pt - py * CROP;
        float ty = (float)py * (1.0f / 13.0f);
        float tx = (float)px * (1.0f / 13.0f);

        float ys = y1n * S + ty * ((y2n - y1n) * S);
        float xs = x1n * S + tx * ((x2n - x1n) * S);

        s_vld[pt] = (ys >= 0.0f && ys <= S && xs >= 0.0f && xs <= S);

        float y0f = floorf(ys), x0f = floorf(xs);
        s_w[pt] = make_float2(xs - x0f, ys - y0f);

        int y0 = (int)y0f; y0 = y0 < 0 ? 0 : (y0 > H - 1 ? H - 1 : y0);
        int yb = y0 + 1;   yb = yb > H - 1 ? H - 1 : yb;
        int x0 = (int)x0f; x0 = x0 < 0 ? 0 : (x0 > H - 1 ? H - 1 : x0);
        int xb = x0 + 1;   xb = xb > H - 1 ? H - 1 : xb;

        int rowT = (b * H + y0) * H;
        int rowB = (b * H + yb) * H;
        s_off[pt] = make_int4((rowT + x0) * C4, (rowT + xb) * C4,
                              (rowB + x0) * C4, (rowB + xb) * C4);
    }
    __syncthreads();

    const float* fm = (lvl == 0) ? f0 : (lvl == 1) ? f1 : (lvl == 2) ? f2 : f3;
    const float4* fv = reinterpret_cast<const float4*>(fm);

    // ---- pipeline prologue: fetch tile 0 ----
    float4 a00, a01, a10, a11;
    float2 wcur;
    int    vcur;
    {
        int4 o = s_off[pin];
        wcur = s_w[pin];
        vcur = s_vld[pin];
        a00 = __ldg(fv + o.x + c4);
        a01 = __ldg(fv + o.y + c4);
        a10 = __ldg(fv + o.z + c4);
        a11 = __ldg(fv + o.w + c4);
    }

    for (int t = 0; t < NT - 1; ++t) {
        // ---- prefetch tile t+1 (unconditional in steady state) ----
        int np = (t + 1) * 4 + pin;
        int4 o = s_off[np];
        float2 wnxt = s_w[np];
        int    vnxt = s_vld[np];
        float4 b00 = __ldg(fv + o.x + c4);
        float4 b01 = __ldg(fv + o.y + c4);
        float4 b10 = __ldg(fv + o.z + c4);
        float4 b11 = __ldg(fv + o.w + c4);

        // ---- compute + store tile t ----
        float wx = wcur.x, wy = wcur.y;
        float ax = 1.0f - wx;
        float ay = 1.0f - wy;

        float4 r;
        r.x = (a00.x * ax + a01.x * wx) * ay + (a10.x * ax + a11.x * wx) * wy;
        r.y = (a00.y * ax + a01.y * wx) * ay + (a10.y * ax + a11.y * wx) * wy;
        r.z = (a00.z * ax + a01.z * wx) * ay + (a10.z * ax + a11.z * wx) * wy;
        r.w = (a00.w * ax + a01.w * wx) * ay + (a10.w * ax + a11.w * wx) * wy;
        if (!vcur) r = make_float4(0.f, 0.f, 0.f, 0.f);
        __stcs(base + t * TS, r);

        // ---- shift ----
        a00 = b00; a01 = b01; a10 = b10; a11 = b11;
        wcur = wnxt; vcur = vnxt;
    }

    // ---- epilogue: tile NT-1 ----
    {
        float wx = wcur.x, wy = wcur.y;
        float ax = 1.0f - wx;
        float ay = 1.0f - wy;

        float4 r;
        r.x = (a00.x * ax + a01.x * wx) * ay + (a10.x * ax + a11.x * wx) * wy;
        r.y = (a00.y * ax + a01.y * wx) * ay + (a10.y * ax + a11.y * wx) * wy;
        r.z = (a00.z * ax + a01.z * wx) * ay + (a10.z * ax + a11.z * wx) * wy;
        r.w = (a00.w * ax + a01.w * wx) * ay + (a10.w * ax + a11.w * wx) * wy;
        if (!vcur) r = make_float4(0.f, 0.f, 0.f, 0.f);
        __stcs(base + (NT - 1) * TS, r);
    }
}

extern "C" void kernel_launch(void* const* d_in, const int* in_sizes, int n_in,
                              void* d_out, int out_size) {
    const float* f0 = (const float*)d_in[0];
    const float* f1 = (const float*)d_in[1];
    const float* f2 = (const float*)d_in[2];
    const float* f3 = (const float*)d_in[3];
    const float* db = (const float*)d_in[4];

    float* out = (float*)d_out;
    float* out_boxes = out + (size_t)NSLOTS * PTS * CCH;

    setup_kernel<<<1, 512>>>(db, out_boxes);
    roi_kernel<<<NSLOTS, 256>>>(f0, f1, f2, f3, db, out);
}

// round 9
// speedup vs baseline: 1.2373x; 1.2373x over previous
#include <cuda_runtime.h>
#include <cuda_bf16.h>

#define NLVL   4
#define BATCH  4
#define NBOX   128
#define MAXBS  64
#define CROP   14
#define CCH    256
#define NSLOTS (NLVL * BATCH * MAXBS)          // 1024
#define PTS    (CROP * CROP)                   // 196
#define C4     (CCH / 4)                       // 64 float4 per point
#define NT     (PTS / 4)                       // 49 tiles of 4 points per slot
#define GT     7                               // tiles per block
#define NGRP   (NT / GT)                       // 7 groups per slot
#define GPTS   (GT * 4)                        // 28 points per block

// slot -> source box index (n in 0..127), or -1 if the slot is empty.
__device__ int g_slot_map[NSLOTS];

// ---------------------------------------------------------------------------
// Setup: 16 warps, one per (batch, level). Warp-ballot prefix scan.
// ---------------------------------------------------------------------------
__global__ void __launch_bounds__(512)
setup_kernel(const float* __restrict__ db, float* __restrict__ out_boxes) {
    int w    = threadIdx.x >> 5;
    int lane = threadIdx.x & 31;
    int b    = w >> 2;
    int lvl  = w & 3;
    float flvl = (float)lvl;

    int rank_base = 0;
    #pragma unroll
    for (int k = 0; k < 4; ++k) {
        int n = k * 32 + lane;
        float id = db[(b * NBOX + n) * 7 + 0];
        bool m = (id == flvl);
        unsigned mask = __ballot_sync(0xffffffffu, m);
        int rank = rank_base + __popc(mask & ((1u << lane) - 1u));
        if (m && rank < MAXBS) {
            g_slot_map[(lvl * BATCH + b) * MAXBS + rank] = n;
            float* ob = out_boxes + ((size_t)(b * NLVL + lvl) * MAXBS + rank) * 6;
            const float* src = db + (b * NBOX + n) * 7 + 1;
            #pragma unroll
            for (int q = 0; q < 6; ++q) ob[q] = src[q];
        }
        rank_base += __popc(mask);
    }
    int filled = rank_base < MAXBS ? rank_base : MAXBS;
    for (int r = filled + lane; r < MAXBS; r += 32) {
        g_slot_map[(lvl * BATCH + b) * MAXBS + r] = -1;
        float* ob = out_boxes + ((size_t)(b * NLVL + lvl) * MAXBS + r) * 6;
        #pragma unroll
        for (int q = 0; q < 6; ++q) ob[q] = 0.0f;
    }
}

// ---------------------------------------------------------------------------
// Main: one block per (slot, tile-group of 7). 256 threads = (pin) x (c4).
// Threads 0..27 precompute this group's 28 points; then a 2-stage register
// pipeline over the 7 tiles: prefetch t+1's gathers while lerping/storing t.
// ---------------------------------------------------------------------------
__global__ void __launch_bounds__(256)
roi_kernel(const float* __restrict__ f0, const float* __restrict__ f1,
           const float* __restrict__ f2, const float* __restrict__ f3,
           const float* __restrict__ db, float* __restrict__ out) {
    __shared__ int4   s_off[GPTS];   // o00,o01,o10,o11 (float4 units)
    __shared__ float2 s_w[GPTS];     // wx, wy
    __shared__ int    s_vld[GPTS];

    int slotIdx = blockIdx.x;
    int grp     = blockIdx.y;                 // 0..6
    int pin     = threadIdx.x >> 6;           // point within tile (0..3)
    int c4      = threadIdx.x & 63;

    // base points at tile (grp*GT), point pin, chunk c4
    float4* base = reinterpret_cast<float4*>(out)
                 + (size_t)slotIdx * (PTS * C4) + (grp * GT * 4 + pin) * C4 + c4;
    const int TS = 4 * C4;                    // tile stride in float4

    int n = g_slot_map[slotIdx];              // uniform across block

    if (n < 0) {                              // empty slot: streaming zeros
        float4 z = make_float4(0.f, 0.f, 0.f, 0.f);
        #pragma unroll
        for (int t = 0; t < GT; ++t) __stcs(base + t * TS, z);
        return;
    }

    int lvl = slotIdx >> 8;
    int b   = (slotIdx >> 6) & 3;
    int H   = 256 >> lvl;

    if (threadIdx.x < GPTS) {
        const float* bx = db + (b * NBOX + n) * 7;
        float cx = bx[1], cy = bx[2], w = bx[3], h = bx[4];

        float y1n = (cy - h * 0.5f) / 1023.0f;
        float y2n = (cy + h * 0.5f) / 1023.0f;
        float x1n = (cx - w * 0.5f) / 1023.0f;
        float x2n = (cx + w * 0.5f) / 1023.0f;

        float S = (float)(H - 1);
        int pt  = grp * GPTS + threadIdx.x;   // global point index
        int py  = pt / CROP;
        int px  = pt - py * CROP;
        float ty = (float)py * (1.0f / 13.0f);
        float tx = (float)px * (1.0f / 13.0f);

        float ys = y1n * S + ty * ((y2n - y1n) * S);
        float xs = x1n * S + tx * ((x2n - x1n) * S);

        s_vld[threadIdx.x] = (ys >= 0.0f && ys <= S && xs >= 0.0f && xs <= S);

        float y0f = floorf(ys), x0f = floorf(xs);
        s_w[threadIdx.x] = make_float2(xs - x0f, ys - y0f);

        int y0 = (int)y0f; y0 = y0 < 0 ? 0 : (y0 > H - 1 ? H - 1 : y0);
        int yb = y0 + 1;   yb = yb > H - 1 ? H - 1 : yb;
        int x0 = (int)x0f; x0 = x0 < 0 ? 0 : (x0 > H - 1 ? H - 1 : x0);
        int xb = x0 + 1;   xb = xb > H - 1 ? H - 1 : xb;

        int rowT = (b * H + y0) * H;
        int rowB = (b * H + yb) * H;
        s_off[threadIdx.x] = make_int4((rowT + x0) * C4, (rowT + xb) * C4,
                                       (rowB + x0) * C4, (rowB + xb) * C4);
    }
    __syncthreads();

    const float* fm = (lvl == 0) ? f0 : (lvl == 1) ? f1 : (lvl == 2) ? f2 : f3;
    const float4* fv = reinterpret_cast<const float4*>(fm);

    // ---- pipeline prologue: fetch local tile 0 ----
    float4 a00, a01, a10, a11;
    float2 wcur;
    int    vcur;
    {
        int4 o = s_off[pin];
        wcur = s_w[pin];
        vcur = s_vld[pin];
        a00 = __ldg(fv + o.x + c4);
        a01 = __ldg(fv + o.y + c4);
        a10 = __ldg(fv + o.z + c4);
        a11 = __ldg(fv + o.w + c4);
    }

    #pragma unroll
    for (int t = 0; t < GT - 1; ++t) {
        // ---- prefetch local tile t+1 ----
        int np = (t + 1) * 4 + pin;
        int4 o = s_off[np];
        float2 wnxt = s_w[np];
        int    vnxt = s_vld[np];
        float4 b00 = __ldg(fv + o.x + c4);
        float4 b01 = __ldg(fv + o.y + c4);
        float4 b10 = __ldg(fv + o.z + c4);
        float4 b11 = __ldg(fv + o.w + c4);

        // ---- compute + store local tile t ----
        float wx = wcur.x, wy = wcur.y;
        float ax = 1.0f - wx;
        float ay = 1.0f - wy;

        float4 r;
        r.x = (a00.x * ax + a01.x * wx) * ay + (a10.x * ax + a11.x * wx) * wy;
        r.y = (a00.y * ax + a01.y * wx) * ay + (a10.y * ax + a11.y * wx) * wy;
        r.z = (a00.z * ax + a01.z * wx) * ay + (a10.z * ax + a11.z * wx) * wy;
        r.w = (a00.w * ax + a01.w * wx) * ay + (a10.w * ax + a11.w * wx) * wy;
        if (!vcur) r = make_float4(0.f, 0.f, 0.f, 0.f);
        __stcs(base + t * TS, r);

        // ---- shift ----
        a00 = b00; a01 = b01; a10 = b10; a11 = b11;
        wcur = wnxt; vcur = vnxt;
    }

    // ---- epilogue: local tile GT-1 ----
    {
        float wx = wcur.x, wy = wcur.y;
        float ax = 1.0f - wx;
        float ay = 1.0f - wy;

        float4 r;
        r.x = (a00.x * ax + a01.x * wx) * ay + (a10.x * ax + a11.x * wx) * wy;
        r.y = (a00.y * ax + a01.y * wx) * ay + (a10.y * ax + a11.y * wx) * wy;
        r.z = (a00.z * ax + a01.z * wx) * ay + (a10.z * ax + a11.z * wx) * wy;
        r.w = (a00.w * ax + a01.w * wx) * ay + (a10.w * ax + a11.w * wx) * wy;
        if (!vcur) r = make_float4(0.f, 0.f, 0.f, 0.f);
        __stcs(base + (GT - 1) * TS, r);
    }
}

extern "C" void kernel_launch(void* const* d_in, const int* in_sizes, int n_in,
                              void* d_out, int out_size) {
    const float* f0 = (const float*)d_in[0];
    const float* f1 = (const float*)d_in[1];
    const float* f2 = (const float*)d_in[2];
    const float* f3 = (const float*)d_in[3];
    const float* db = (const float*)d_in[4];

    float* out = (float*)d_out;
    float* out_boxes = out + (size_t)NSLOTS * PTS * CCH;

    setup_kernel<<<1, 512>>>(db, out_boxes);
    dim3 grid(NSLOTS, NGRP);
    roi_kernel<<<grid, 256>>>(f0, f1, f2, f3, db, out);
}

// round 10
// speedup vs baseline: 1.2914x; 1.0437x over previous
#include <cuda_runtime.h>
#include <cuda_bf16.h>

#define NLVL   4
#define BATCH  4
#define NBOX   128
#define MAXBS  64
#define CROP   14
#define CCH    256
#define NSLOTS (NLVL * BATCH * MAXBS)          // 1024
#define PTS    (CROP * CROP)                   // 196
#define C4     (CCH / 4)                       // 64 float4 per point
#define NT     (PTS / 4)                       // 49 tiles of 4 points per slot
#define GT     7                               // tiles per block
#define NGRP   (NT / GT)                       // 7 groups per slot
#define GPTS   (GT * 4)                        // 28 points per block

// ---------------------------------------------------------------------------
// Single fused kernel: one block per (slot, tile-group of 7).
// Warp 0 re-derives the rank->box map for this block's (b,lvl) via a
// warp-ballot prefix scan (L2-hot after the first wave). The 16 blocks with
// (grp==0, rank==0) also write their (b,lvl) stripe of the boxes output.
// Then: threads 0..27 precompute this group's 28 points; 2-stage register
// pipeline over the 7 tiles (prefetch t+1's gathers while lerping/storing t).
// ---------------------------------------------------------------------------
__global__ void __launch_bounds__(256)
roi_kernel(const float* __restrict__ f0, const float* __restrict__ f1,
           const float* __restrict__ f2, const float* __restrict__ f3,
           const float* __restrict__ db, float* __restrict__ out) {
    __shared__ int    s_map[MAXBS];  // rank -> box index
    __shared__ int    s_filled;
    __shared__ int4   s_off[GPTS];   // o00,o01,o10,o11 (float4 units)
    __shared__ float2 s_w[GPTS];     // wx, wy
    __shared__ int    s_vld[GPTS];

    int slotIdx = blockIdx.x;
    int grp     = blockIdx.y;                 // 0..6
    int pin     = threadIdx.x >> 6;           // point within tile (0..3)
    int c4      = threadIdx.x & 63;
    int lane    = threadIdx.x & 31;

    int lvl  = slotIdx >> 8;
    int b    = (slotIdx >> 6) & 3;
    int rank = slotIdx & 63;

    // ---- warp 0: ballot prefix scan over this (b,lvl)'s 128 boxes ----
    if (threadIdx.x < 32) {
        float flvl = (float)lvl;
        int rank_base = 0;
        #pragma unroll
        for (int k = 0; k < 4; ++k) {
            int n = k * 32 + lane;
            float id = __ldg(db + (b * NBOX + n) * 7 + 0);
            bool m = (id == flvl);
            unsigned mask = __ballot_sync(0xffffffffu, m);
            int r = rank_base + __popc(mask & ((1u << lane) - 1u));
            if (m && r < MAXBS) s_map[r] = n;
            rank_base += __popc(mask);
        }
        if (lane == 0) s_filled = rank_base < MAXBS ? rank_base : MAXBS;
    }
    __syncthreads();

    int filled = s_filled;
    int n = (rank < filled) ? s_map[rank] : -1;

    // ---- boxes output: 16 designated blocks write their (b,lvl) stripe ----
    if (grp == 0 && rank == 0) {
        // boxes live after the fmap region: [B][NLVL*MAXBS][6]
        float* ob_base = out + (size_t)NSLOTS * PTS * CCH
                       + ((size_t)(b * NLVL + lvl) * MAXBS) * 6;
        // 64 slots x 6 floats = 384 values; 256 threads, 2 passes
        for (int i = threadIdx.x; i < MAXBS * 6; i += 256) {
            int r = i / 6;
            int q = i - r * 6;
            float v = 0.0f;
            if (r < filled) v = __ldg(db + (b * NBOX + s_map[r]) * 7 + 1 + q);
            ob_base[i] = v;
        }
    }

    float4* base = reinterpret_cast<float4*>(out)
                 + (size_t)slotIdx * (PTS * C4) + (grp * GT * 4 + pin) * C4 + c4;
    const int TS = 4 * C4;                    // tile stride in float4

    if (n < 0) {                              // empty slot: streaming zeros
        float4 z = make_float4(0.f, 0.f, 0.f, 0.f);
        #pragma unroll
        for (int t = 0; t < GT; ++t) __stcs(base + t * TS, z);
        return;
    }

    int H = 256 >> lvl;

    if (threadIdx.x < GPTS) {
        const float* bx = db + (b * NBOX + n) * 7;
        float cx = bx[1], cy = bx[2], w = bx[3], h = bx[4];

        float y1n = (cy - h * 0.5f) / 1023.0f;
        float y2n = (cy + h * 0.5f) / 1023.0f;
        float x1n = (cx - w * 0.5f) / 1023.0f;
        float x2n = (cx + w * 0.5f) / 1023.0f;

        float S = (float)(H - 1);
        int pt  = grp * GPTS + threadIdx.x;   // global point index
        int py  = pt / CROP;
        int px  = pt - py * CROP;
        float ty = (float)py * (1.0f / 13.0f);
        float tx = (float)px * (1.0f / 13.0f);

        float ys = y1n * S + ty * ((y2n - y1n) * S);
        float xs = x1n * S + tx * ((x2n - x1n) * S);

        s_vld[threadIdx.x] = (ys >= 0.0f && ys <= S && xs >= 0.0f && xs <= S);

        float y0f = floorf(ys), x0f = floorf(xs);
        s_w[threadIdx.x] = make_float2(xs - x0f, ys - y0f);

        int y0 = (int)y0f; y0 = y0 < 0 ? 0 : (y0 > H - 1 ? H - 1 : y0);
        int yb = y0 + 1;   yb = yb > H - 1 ? H - 1 : yb;
        int x0 = (int)x0f; x0 = x0 < 0 ? 0 : (x0 > H - 1 ? H - 1 : x0);
        int xb = x0 + 1;   xb = xb > H - 1 ? H - 1 : xb;

        int rowT = (b * H + y0) * H;
        int rowB = (b * H + yb) * H;
        s_off[threadIdx.x] = make_int4((rowT + x0) * C4, (rowT + xb) * C4,
                                       (rowB + x0) * C4, (rowB + xb) * C4);
    }
    __syncthreads();

    const float* fm = (lvl == 0) ? f0 : (lvl == 1) ? f1 : (lvl == 2) ? f2 : f3;
    const float4* fv = reinterpret_cast<const float4*>(fm);

    // ---- pipeline prologue: fetch local tile 0 ----
    float4 a00, a01, a10, a11;
    float2 wcur;
    int    vcur;
    {
        int4 o = s_off[pin];
        wcur = s_w[pin];
        vcur = s_vld[pin];
        a00 = __ldg(fv + o.x + c4);
        a01 = __ldg(fv + o.y + c4);
        a10 = __ldg(fv + o.z + c4);
        a11 = __ldg(fv + o.w + c4);
    }

    #pragma unroll
    for (int t = 0; t < GT - 1; ++t) {
        // ---- prefetch local tile t+1 ----
        int np = (t + 1) * 4 + pin;
        int4 o = s_off[np];
        float2 wnxt = s_w[np];
        int    vnxt = s_vld[np];
        float4 b00 = __ldg(fv + o.x + c4);
        float4 b01 = __ldg(fv + o.y + c4);
        float4 b10 = __ldg(fv + o.z + c4);
        float4 b11 = __ldg(fv + o.w + c4);

        // ---- compute + store local tile t ----
        float wx = wcur.x, wy = wcur.y;
        float ax = 1.0f - wx;
        float ay = 1.0f - wy;

        float4 r;
        r.x = (a00.x * ax + a01.x * wx) * ay + (a10.x * ax + a11.x * wx) * wy;
        r.y = (a00.y * ax + a01.y * wx) * ay + (a10.y * ax + a11.y * wx) * wy;
        r.z = (a00.z * ax + a01.z * wx) * ay + (a10.z * ax + a11.z * wx) * wy;
        r.w = (a00.w * ax + a01.w * wx) * ay + (a10.w * ax + a11.w * wx) * wy;
        if (!vcur) r = make_float4(0.f, 0.f, 0.f, 0.f);
        __stcs(base + t * TS, r);

        // ---- shift ----
        a00 = b00; a01 = b01; a10 = b10; a11 = b11;
        wcur = wnxt; vcur = vnxt;
    }

    // ---- epilogue: local tile GT-1 ----
    {
        float wx = wcur.x, wy = wcur.y;
        float ax = 1.0f - wx;
        float ay = 1.0f - wy;

        float4 r;
        r.x = (a00.x * ax + a01.x * wx) * ay + (a10.x * ax + a11.x * wx) * wy;
        r.y = (a00.y * ax + a01.y * wx) * ay + (a10.y * ax + a11.y * wx) * wy;
        r.z = (a00.z * ax + a01.z * wx) * ay + (a10.z * ax + a11.z * wx) * wy;
        r.w = (a00.w * ax + a01.w * wx) * ay + (a10.w * ax + a11.w * wx) * wy;
        if (!vcur) r = make_float4(0.f, 0.f, 0.f, 0.f);
        __stcs(base + (GT - 1) * TS, r);
    }
}

extern "C" void kernel_launch(void* const* d_in, const int* in_sizes, int n_in,
                              void* d_out, int out_size) {
    const float* f0 = (const float*)d_in[0];
    const float* f1 = (const float*)d_in[1];
    const float* f2 = (const float*)d_in[2];
    const float* f3 = (const float*)d_in[3];
    const float* db = (const float*)d_in[4];

    float* out = (float*)d_out;

    dim3 grid(NSLOTS, NGRP);
    roi_kernel<<<grid, 256>>>(f0, f1, f2, f3, db, out);
}